// round 17
// baseline (speedup 1.0000x reference)
#include <cuda_runtime.h>
#include <cuda_fp16.h>
#include <math.h>
#include <stdint.h>

#define BATCH 2
#define SEQ 1024
#define FEAT 80
#define DMODEL 512
#define DSTATE 16
#define DCONV 7
#define HEADDIM 64
#define DINNER 1024
#define NHEADS 16
#define CONVDIM 1056
#define DINPROJ 2096
#define NTOK (BATCH*SEQ)
#define EPSF 1e-5f
#define KPI 128
#define CH 16            // scan chunks
#define CL 64            // steps per chunk

// ---------------- scratch ----------------
__device__ float g_h[NTOK*DMODEL];
__device__ float g_zx[2][NTOK*DINPROJ];
__device__ float g_xbc[2][NTOK*CONVDIM];    // only BC part (cols 1024..1055) used now
__device__ float g_y[2][NTOK*DINNER];
__device__ float g_ytmp[4][NTOK*DMODEL];    // [dir*2 + khalf]

__device__ float g_S[2*2*16*CH*64*16];
__device__ float g_cA[2][NTOK*NHEADS];

__device__ __half g_hnh[NTOK*DMODEL],  g_hnl[NTOK*DMODEL];
__device__ __half g_xh[NTOK*KPI],      g_xl[NTOK*KPI];
__device__ __half g_yh[2][NTOK*DINNER],g_yl[2][NTOK*DINNER];
__device__ __half g_hfh[NTOK*DMODEL],  g_hfl[NTOK*DMODEL];

// weights: hi-only fp16, [K][N] layout, K padded where needed
__device__ __half g_winh[4L*DMODEL*DINPROJ];
__device__ __half g_wouth[4L*DINNER*DMODEL];
__device__ __half g_wpih[KPI*DMODEL];
__device__ __half g_wpoh[DMODEL*FEAT];

// ---------------- helpers ----------------
__device__ __forceinline__ void cvt_hl(float v, __half& h, __half& l) {
    h = __float2half_rn(v);
    l = __float2half_rn(v - __half2float(h));
}
__device__ __forceinline__ uint32_t smem_u32(const void* p) {
    uint32_t a;
    asm("{ .reg .u64 t; cvta.to.shared.u64 t, %1; cvt.u32.u64 %0, t; }" : "=r"(a) : "l"(p));
    return a;
}
__device__ __forceinline__ void cpa16(uint32_t dst, const void* src) {
    asm volatile("cp.async.cg.shared.global [%0], [%1], 16;" :: "r"(dst), "l"(src));
}
__device__ __forceinline__ void ldsm_x4(unsigned r[4], uint32_t addr) {
    asm volatile("ldmatrix.sync.aligned.m8n8.x4.shared.b16 {%0,%1,%2,%3}, [%4];"
        : "=r"(r[0]), "=r"(r[1]), "=r"(r[2]), "=r"(r[3]) : "r"(addr));
}
__device__ __forceinline__ void ldsm_x4t(unsigned r[4], uint32_t addr) {
    asm volatile("ldmatrix.sync.aligned.m8n8.x4.trans.shared.b16 {%0,%1,%2,%3}, [%4];"
        : "=r"(r[0]), "=r"(r[1]), "=r"(r[2]), "=r"(r[3]) : "r"(addr));
}
__device__ __forceinline__ void mma16816h(float d[4], const unsigned a[4], const unsigned b[2]) {
    asm volatile("mma.sync.aligned.m16n8k16.row.col.f32.f16.f16.f32 "
        "{%0,%1,%2,%3}, {%4,%5,%6,%7}, {%8,%9}, {%0,%1,%2,%3};"
        : "+f"(d[0]), "+f"(d[1]), "+f"(d[2]), "+f"(d[3])
        : "r"(a[0]), "r"(a[1]), "r"(a[2]), "r"(a[3]), "r"(b[0]), "r"(b[1]));
}

// ---------------- GEMM: BM=128, BN=128, BK=64, 256 thr, 2 CTAs/SM ----------
// (R16 config: warp grid 4(M) x 2(N), fp16 2-pass, 2-stage cp.async.)
#define ASTR 144
#define BSTR 272
#define OFF_AL 18432
#define OFF_BH 36864
#define STAGE 54272
#define GSMEM (2*STAGE)

__device__ __forceinline__ void g5_stage(
    uint32_t sb, const __half* Ah, const __half* Al, const __half* Bh,
    int m0, int n0, int k0, int N, int lda, int tid)
{
    #pragma unroll
    for (int q = 0; q < 4; q++) {
        int idx = q * 256 + tid, row = idx >> 3, seg = idx & 7;
        uint32_t d = sb + row * ASTR + seg * 16;
        const __half* s = Ah + (size_t)(m0 + row) * lda + k0 + seg * 8;
        cpa16(d, s);
        cpa16(d + OFF_AL, Al + (s - Ah));
    }
    #pragma unroll
    for (int q = 0; q < 4; q++) {
        int idx = q * 256 + tid, row = idx >> 4, seg = idx & 15;
        uint32_t d = sb + OFF_BH + row * BSTR + seg * 16;
        if (n0 + seg * 8 < N) {
            cpa16(d, Bh + (size_t)(k0 + row) * N + n0 + seg * 8);
        } else {
            asm volatile("st.shared.v4.b32 [%0], {%1,%1,%1,%1};" :: "r"(d), "r"(0) : "memory");
        }
    }
    asm volatile("cp.async.commit_group;" ::: "memory");
}

template<bool ACCUM, bool BIAS>
__global__ void __launch_bounds__(256, 2) gemm5(
    const __half* __restrict__ Ah, const __half* __restrict__ Al,
    const __half* __restrict__ Bh,
    const float* __restrict__ bias, float* __restrict__ C,
    int N, int K, int lda,
    long azH, long bzH, long czH,
    long azL, long bzL, long czL, int zdiv)
{
    extern __shared__ char dsm[];
    const int zh = blockIdx.z / zdiv, zl = blockIdx.z % zdiv;
    Ah += (long)zh * azH + (long)zl * azL;
    Al += (long)zh * azH + (long)zl * azL;
    Bh += (long)zh * bzH + (long)zl * bzL;
    C  += (long)zh * czH + (long)zl * czL;
    const int m0 = blockIdx.y * 128, n0 = blockIdx.x * 128;
    const int tid = threadIdx.x, warp = tid >> 5, lane = tid & 31;
    const int wm = (warp & 3) * 32, wn = (warp >> 2) * 64;
    const uint32_t raw = smem_u32(dsm);

    float acc[2][8][4];
    #pragma unroll
    for (int f = 0; f < 2; f++)
        #pragma unroll
        for (int g = 0; g < 8; g++)
            #pragma unroll
            for (int i = 0; i < 4; i++) acc[f][g][i] = 0.f;

    const int nch = K >> 6;
    g5_stage(raw, Ah, Al, Bh, m0, n0, 0, N, lda, tid);

    for (int c = 0; c < nch; c++) {
        asm volatile("cp.async.wait_group 0;" ::: "memory");
        __syncthreads();
        if (c + 1 < nch)
            g5_stage(raw + (uint32_t)((c + 1) & 1) * STAGE,
                     Ah, Al, Bh, m0, n0, (c + 1) << 6, N, lda, tid);

        const uint32_t sb = raw + (uint32_t)(c & 1) * STAGE;
        #pragma unroll
        for (int ks = 0; ks < 4; ks++) {
            const int kk = ks * 16;
            unsigned ah[2][4], al[2][4], bh[8][2];
            #pragma unroll
            for (int f = 0; f < 2; f++) {
                int row = wm + f * 16 + (lane & 15);
                int col = kk + ((lane >> 4) << 3);
                uint32_t a = sb + row * ASTR + col * 2;
                ldsm_x4(ah[f], a);
                ldsm_x4(al[f], a + OFF_AL);
            }
            #pragma unroll
            for (int gp = 0; gp < 4; gp++) {
                int row = kk + (lane & 15);
                int col = wn + gp * 16 + ((lane >> 4) << 3);
                unsigned t4[4];
                ldsm_x4t(t4, sb + OFF_BH + row * BSTR + col * 2);
                bh[gp * 2][0] = t4[0]; bh[gp * 2][1] = t4[1];
                bh[gp * 2 + 1][0] = t4[2]; bh[gp * 2 + 1][1] = t4[3];
            }
            #pragma unroll
            for (int f = 0; f < 2; f++)
                #pragma unroll
                for (int g = 0; g < 8; g++) {
                    mma16816h(acc[f][g], ah[f], bh[g]);
                    mma16816h(acc[f][g], al[f], bh[g]);
                }
        }
    }

    const int cr = lane >> 2, cc = (lane & 3) * 2;
    #pragma unroll
    for (int f = 0; f < 2; f++) {
        #pragma unroll
        for (int g = 0; g < 8; g++) {
            int mmb = m0 + wm + f * 16 + cr;
            int nn = n0 + wn + g * 8 + cc;
            #pragma unroll
            for (int half = 0; half < 2; half++) {
                int m = mmb + half * 8;
                #pragma unroll
                for (int j = 0; j < 2; j++) {
                    if (nn + j < N) {
                        float v = acc[f][g][half * 2 + j];
                        long o = (long)m * N + nn + j;
                        if (BIAS) v += bias[nn + j];
                        if (ACCUM) v += C[o];
                        C[o] = v;
                    }
                }
            }
        }
    }
}

// ---------------- mega convert: weights (hi) + x (hi/lo) -> fp16 -----------
#define SEG0 ((long)KPI*DMODEL)
#define SEG1 (SEG0 + 4L*DMODEL*DINPROJ)
#define SEG2 (SEG1 + 4L*DINNER*DMODEL)
#define SEG3 (SEG2 + (long)DMODEL*FEAT)
#define SEG4 (SEG3 + (long)NTOK*KPI)

__global__ void __launch_bounds__(256) cvt_all_k(
    const float* __restrict__ Wpi, const float* __restrict__ Win,
    const float* __restrict__ Wout, const float* __restrict__ Wpo,
    const float* __restrict__ x)
{
    long i = (long)blockIdx.x * 256 + threadIdx.x;
    if (i >= SEG4) return;
    if (i < SEG0) {
        long k = i / DMODEL, n = i - k * DMODEL;
        float v = (k < FEAT) ? Wpi[k * DMODEL + n] : 0.f;
        g_wpih[i] = __float2half_rn(v);
    } else if (i < SEG1) {
        long o = i - SEG0;
        g_winh[o] = __float2half_rn(Win[o]);
    } else if (i < SEG2) {
        long o = i - SEG1;
        g_wouth[o] = __float2half_rn(Wout[o]);
    } else if (i < SEG3) {
        long o = i - SEG2;
        g_wpoh[o] = __float2half_rn(Wpo[o]);
    } else {
        long o = i - SEG3;
        long r = o >> 7, c = o & (KPI - 1);
        float v = (c < FEAT) ? x[r * FEAT + c] : 0.f;
        __half h, l;
        cvt_hl(v, h, l);
        g_xh[o] = h; g_xl[o] = l;
    }
}

// ---------------- reductions ----------------
__device__ __forceinline__ float warpSum(float v) {
    #pragma unroll
    for (int o = 16; o; o >>= 1) v += __shfl_down_sync(0xffffffffu, v, o);
    return v;
}

// ---------------- layernorm (+optional 4-way residual add) -> fp16 hi/lo ---
template<bool RES>
__global__ void __launch_bounds__(256) layernorm_hl_k(
    float* __restrict__ hio, const float* __restrict__ ytbase,
    const float* __restrict__ w, const float* __restrict__ b,
    __half* __restrict__ oh, __half* __restrict__ ol,
    float* __restrict__ of)
{
    __shared__ float sbuf[8];
    int row = blockIdx.x, tid = threadIdx.x;
    long o0 = (long)row * DMODEL + tid, o1 = o0 + 256;
    float x0 = hio[o0], x1 = hio[o1];
    if (RES) {
        #pragma unroll
        for (int r = 0; r < 4; r++) {
            x0 += ytbase[(long)r * NTOK * DMODEL + o0];
            x1 += ytbase[(long)r * NTOK * DMODEL + o1];
        }
        hio[o0] = x0; hio[o1] = x1;
    }
    float s = warpSum(x0 + x1);
    if ((tid & 31) == 0) sbuf[tid >> 5] = s;
    __syncthreads();
    float mean = 0.f;
    #pragma unroll
    for (int i = 0; i < 8; i++) mean += sbuf[i];
    mean *= (1.f / DMODEL);
    __syncthreads();
    float c0 = x0 - mean, c1 = x1 - mean;
    float ss = warpSum(c0 * c0 + c1 * c1);
    if ((tid & 31) == 0) sbuf[tid >> 5] = ss;
    __syncthreads();
    float var = 0.f;
    #pragma unroll
    for (int i = 0; i < 8; i++) var += sbuf[i];
    var *= (1.f / DMODEL);
    float rs = rsqrtf(var + EPSF);
    float r0 = c0 * rs * w[tid] + b[tid];
    float r1 = c1 * rs * w[tid + 256] + b[tid + 256];
    __half h, l;
    cvt_hl(r0, h, l); oh[o0] = h; ol[o0] = l;
    cvt_hl(r1, h, l); oh[o1] = h; ol[o1] = l;
    if (of) { of[o0] = r0; of[o1] = r1; }
}

// ---------------- B/C-only sliding-window conv + SiLU ----------------
// grid: (SEQ/64 seq-tiles, 4 = dir*2+b); 32 threads = BC channels 1024..1055
__global__ void __launch_bounds__(32) convbc_k(
    const float* __restrict__ convw, const float* __restrict__ convb, int l)
{
    int c = 1024 + threadIdx.x;
    int t0 = blockIdx.x * 64;
    int dir = blockIdx.y >> 1;
    int b = blockIdx.y & 1;
    const float* wp = convw + ((long)((l * 2 + dir) * CONVDIM) + c) * DCONV;
    float w[7];
    #pragma unroll
    for (int k = 0; k < 7; k++) w[k] = wp[k];
    float bias = convb[(l * 2 + dir) * CONVDIM + c];
    const float* in = g_zx[dir] + (long)b * SEQ * DINPROJ + DINNER + c;
    float* outp = g_xbc[dir] + (long)b * SEQ * CONVDIM + c;

    float win[7];
    // win[j] = in[orig(t-j)]; unified shift for both dirs
    #pragma unroll
    for (int j = 1; j < 7; j++) {
        int ts = t0 - j;
        if (ts >= 0) { int o = dir ? (SEQ - 1 - ts) : ts; win[j] = in[(long)o * DINPROJ]; }
        else win[j] = 0.f;
    }
    #pragma unroll 4
    for (int i = 0; i < 64; i++) {
        int t = t0 + i;
        int o = dir ? (SEQ - 1 - t) : t;
        win[0] = in[(long)o * DINPROJ];
        float a = bias;
        #pragma unroll
        for (int j = 0; j < 7; j++) a += w[6 - j] * win[j];
        float sv = a / (1.f + expf(-a));
        outp[(long)o * CONVDIM] = sv;
        #pragma unroll
        for (int j = 6; j > 0; j--) win[j] = win[j - 1];
    }
}

// ---------------- scan phase A: inline x-conv + chunk-local scan -----------
// grid: 1024 = dir*512 + b*256 + h*16 + chunk; 64 threads (p)
__global__ void __launch_bounds__(64) scanA_k(
    const float* __restrict__ Dp, const float* __restrict__ dt_bias,
    const float* __restrict__ A_log, const float* __restrict__ convw,
    const float* __restrict__ convb, int l)
{
    int bid = blockIdx.x;
    int chunk = bid & 15;
    int h = (bid >> 4) & 15;
    int b = (bid >> 8) & 1;
    int dir = bid >> 9;
    int p = threadIdx.x;
    int cc = h * HEADDIM + p;                 // x channel
    const float* xbc = g_xbc[dir];
    const float* zx = g_zx[dir];
    float* yo = g_y[dir];
    float* cAo = g_cA[dir];
    const float Dv = Dp[(l * 2 + dir) * NHEADS + h];
    const float dtb = dt_bias[(l * 2 + dir) * NHEADS + h];
    const float Av = -expf(A_log[(l * 2 + dir) * NHEADS + h]);

    // conv params for this x channel
    const float* wp = convw + ((long)((l * 2 + dir) * CONVDIM) + cc) * DCONV;
    float wv[7];
    #pragma unroll
    for (int k = 0; k < 7; k++) wv[k] = wp[k];
    const float cb = convb[(l * 2 + dir) * CONVDIM + cc];
    const float* inx = zx + (long)(b * SEQ) * DINPROJ + DINNER + cc;

    __shared__ float sdt64[64], sdA64[64];
    {
        int t = chunk * CL + p;
        int o = dir ? (SEQ - 1 - t) : t;
        float raw = zx[(long)(b * SEQ + o) * DINPROJ + DINNER + CONVDIM + h];
        float xv = raw + dtb;
        float dt = (xv > 20.f) ? xv : log1pf(expf(xv));
        sdt64[p] = dt;
        sdA64[p] = expf(dt * Av);
    }
    __syncthreads();

    // window warm-up: win[j] = in[orig(t0-j)]
    float win[7];
    int t0c = chunk * CL;
    #pragma unroll
    for (int j = 1; j < 7; j++) {
        int ts = t0c - j;
        if (ts >= 0) { int o = dir ? (SEQ - 1 - ts) : ts; win[j] = inx[(long)o * DINPROJ]; }
        else win[j] = 0.f;
    }

    float hs[16];
    #pragma unroll
    for (int n = 0; n < 16; n++) hs[n] = 0.f;
    float cumA = 1.f;
    __shared__ float sB[8][16], sC[8][16];

    for (int t8 = 0; t8 < CL; t8 += 8) {
        int tb = chunk * CL + t8;
        #pragma unroll
        for (int i = p; i < 128; i += 64) {
            int tt = i >> 4, n = i & 15;
            int o = dir ? (SEQ - 1 - (tb + tt)) : (tb + tt);
            long base = (long)(b * SEQ + o) * CONVDIM + DINNER;
            sB[tt][n] = xbc[base + n];
            sC[tt][n] = xbc[base + DSTATE + n];
        }
        __syncthreads();

        float nv[8];
        int oidx[8];
        #pragma unroll
        for (int j = 0; j < 8; j++) {
            int o = dir ? (SEQ - 1 - (tb + j)) : (tb + j);
            oidx[j] = o;
            nv[j] = inx[(long)o * DINPROJ];
        }
        #pragma unroll
        for (int j = 0; j < 8; j++) {
            // inline conv + silu
            win[0] = nv[j];
            float a = cb;
            #pragma unroll
            for (int jj = 0; jj < 7; jj++) a += wv[6 - jj] * win[jj];
            float xt = a / (1.f + expf(-a));
            #pragma unroll
            for (int jj = 6; jj > 0; jj--) win[jj] = win[jj - 1];

            float dt = sdt64[t8 + j], dA = sdA64[t8 + j];
            float cdt = dt * xt;
            float y = 0.f;
            #pragma unroll
            for (int n = 0; n < 16; n++) {
                hs[n] = hs[n] * dA + cdt * sB[j][n];
                y += hs[n] * sC[j][n];
            }
            y += Dv * xt;
            yo[(long)(b * SEQ + oidx[j]) * DINNER + h * HEADDIM + p] = y;  // pre-gate
            cumA *= dA;
            if (p == 0) cAo[((long)(b * SEQ) + tb + j) * NHEADS + h] = cumA;
        }
        __syncthreads();
    }
    long sbase = ((((long)(dir * 2 + b) * 16 + h) * CH + chunk) * 64 + p) * 16;
    #pragma unroll
    for (int n = 0; n < 16; n++) g_S[sbase + n] = hs[n];
}

// ---------------- scan phase C: inline chunk-prefix + fixup + gate ---------
__global__ void __launch_bounds__(64) scanC_k(int l)
{
    int bid = blockIdx.x;
    int chunk = bid & 15;
    int h = (bid >> 4) & 15;
    int b = (bid >> 8) & 1;
    int dir = bid >> 9;
    int p = threadIdx.x;
    const float* xbc = g_xbc[dir];
    const float* zx = g_zx[dir];
    const float* cAo = g_cA[dir];
    float* yo = g_y[dir];

    // prefix over chunks < chunk (same FMA order as the old scanB)
    float H[16];
    #pragma unroll
    for (int n = 0; n < 16; n++) H[n] = 0.f;
    long sOff = (((long)(dir * 2 + b) * 16 + h) * CH) * 64 * 16;
    for (int c2 = 0; c2 < chunk; c2++) {
        const float* Sp = g_S + sOff + ((long)c2 * 64 + p) * 16;
        float P = cAo[((long)(b * SEQ) + c2 * CL + CL - 1) * NHEADS + h];
        #pragma unroll
        for (int n = 0; n < 16; n++) H[n] = P * H[n] + Sp[n];
    }

    __shared__ float sC[8][16], scA[8];

    for (int t8 = 0; t8 < CL; t8 += 8) {
        int tb = chunk * CL + t8;
        #pragma unroll
        for (int i = p; i < 128; i += 64) {
            int tt = i >> 4, n = i & 15;
            int o = dir ? (SEQ - 1 - (tb + tt)) : (tb + tt);
            sC[tt][n] = xbc[(long)(b * SEQ + o) * CONVDIM + DINNER + DSTATE + n];
        }
        if (p < 8)
            scA[p] = cAo[((long)(b * SEQ) + tb + p) * NHEADS + h];
        __syncthreads();

        float yp[8], zt[8];
        int oidx[8];
        #pragma unroll
        for (int j = 0; j < 8; j++) {
            int o = dir ? (SEQ - 1 - (tb + j)) : (tb + j);
            oidx[j] = o;
            yp[j] = yo[(long)(b * SEQ + o) * DINNER + h * HEADDIM + p];
            zt[j] = zx[(long)(b * SEQ + o) * DINPROJ + h * HEADDIM + p];
        }
        #pragma unroll
        for (int j = 0; j < 8; j++) {
            float dot = 0.f;
            #pragma unroll
            for (int n = 0; n < 16; n++) dot += H[n] * sC[j][n];
            float y = yp[j] + scA[j] * dot;
            float z = zt[j];
            float sil = z / (1.f + expf(-z));
            yo[(long)(b * SEQ + oidx[j]) * DINNER + h * HEADDIM + p] = y * sil;
        }
        __syncthreads();
    }
}

// ---------------- RMS norm (1024) -> fp16 hi/lo (per dir) ------------------
__global__ void __launch_bounds__(256) rms_hl_k(const float* __restrict__ normw, int l)
{
    __shared__ float sbuf[8];
    int bid = blockIdx.x;
    int dir = bid >> 11;
    int tok = bid & (NTOK - 1);
    int tid = threadIdx.x;
    const float* v = g_y[dir] + (long)tok * DINNER;
    const float* w = normw + (l * 2 + dir) * DINNER;
    float vals[4];
    float ss = 0.f;
    #pragma unroll
    for (int i = 0; i < 4; i++) {
        vals[i] = v[tid + i * 256];
        ss += vals[i] * vals[i];
    }
    ss = warpSum(ss);
    if ((tid & 31) == 0) sbuf[tid >> 5] = ss;
    __syncthreads();
    float tot = 0.f;
    #pragma unroll
    for (int i = 0; i < 8; i++) tot += sbuf[i];
    float rs = rsqrtf(tot * (1.f / DINNER) + EPSF);
    #pragma unroll
    for (int i = 0; i < 4; i++) {
        float sv = vals[i] * rs * w[tid + i * 256];
        __half h, l2;
        cvt_hl(sv, h, l2);
        long o = (long)tok * DINNER + tid + i * 256;
        g_yh[dir][o] = h;
        g_yl[dir][o] = l2;
    }
}

// ---------------- launch ----------------
extern "C" void kernel_launch(void* const* d_in, const int* in_sizes, int n_in,
                              void* d_out, int out_size)
{
    const float* x      = (const float*)d_in[0];
    const float* Wpi    = (const float*)d_in[1];
    const float* bpi    = (const float*)d_in[2];
    const float* ln_w   = (const float*)d_in[3];
    const float* ln_b   = (const float*)d_in[4];
    const float* Win    = (const float*)d_in[5];
    const float* convw  = (const float*)d_in[6];
    const float* convb  = (const float*)d_in[7];
    const float* dt_bias= (const float*)d_in[8];
    const float* A_log  = (const float*)d_in[9];
    const float* Dp     = (const float*)d_in[10];
    const float* normw  = (const float*)d_in[11];
    const float* Wout   = (const float*)d_in[12];
    const float* fn_w   = (const float*)d_in[13];
    const float* fn_b   = (const float*)d_in[14];
    const float* Wpo    = (const float*)d_in[15];
    const float* bpo    = (const float*)d_in[16];
    float* out = (float*)d_out;

    cudaFuncSetAttribute(gemm5<false, true>,  cudaFuncAttributeMaxDynamicSharedMemorySize, GSMEM);
    cudaFuncSetAttribute(gemm5<false, false>, cudaFuncAttributeMaxDynamicSharedMemorySize, GSMEM);

    float *ph, *pzx, *pyt;
    __half *pxh, *pxl, *phnh, *phnl, *pyh, *pyl, *phfh, *phfl;
    __half *pwinh, *pwouth, *pwpih, *pwpoh;
    cudaGetSymbolAddress((void**)&ph,     g_h);
    cudaGetSymbolAddress((void**)&pzx,    g_zx);
    cudaGetSymbolAddress((void**)&pyt,    g_ytmp);
    cudaGetSymbolAddress((void**)&pxh,    g_xh);
    cudaGetSymbolAddress((void**)&pxl,    g_xl);
    cudaGetSymbolAddress((void**)&phnh,   g_hnh);
    cudaGetSymbolAddress((void**)&phnl,   g_hnl);
    cudaGetSymbolAddress((void**)&pyh,    g_yh);
    cudaGetSymbolAddress((void**)&pyl,    g_yl);
    cudaGetSymbolAddress((void**)&phfh,   g_hfh);
    cudaGetSymbolAddress((void**)&phfl,   g_hfl);
    cudaGetSymbolAddress((void**)&pwinh,  g_winh);
    cudaGetSymbolAddress((void**)&pwouth, g_wouth);
    cudaGetSymbolAddress((void**)&pwpih,  g_wpih);
    cudaGetSymbolAddress((void**)&pwpoh,  g_wpoh);

    // ---- one mega convert (weights hi + x hi/lo) ----
    cvt_all_k<<<(int)((SEG4 + 255) / 256), 256>>>(Wpi, Win, Wout, Wpo, x);

    // ---- input proj: h = x @ Wpi + bpi ----
    gemm5<false, true><<<dim3(4, 16, 1), 256, GSMEM>>>(
        pxh, pxl, pwpih, bpi, ph, DMODEL, KPI, KPI,
        0, 0, 0, 0, 0, 0, 1);

    for (int l = 0; l < 2; l++) {
        if (l == 0)
            layernorm_hl_k<false><<<NTOK, 256>>>(ph, nullptr,
                ln_w, ln_b, phnh, phnl, nullptr);
        else
            layernorm_hl_k<true><<<NTOK, 256>>>(ph, pyt,
                ln_w + l*DMODEL, ln_b + l*DMODEL, phnh, phnl, nullptr);
        // in-proj: z = dir
        gemm5<false, false><<<dim3(17, 16, 2), 256, GSMEM>>>(
            phnh, phnl,
            pwinh + (long)l*2*DMODEL*DINPROJ,
            nullptr, pzx, DINPROJ, DMODEL, DMODEL,
            0, (long)DMODEL*DINPROJ, (long)NTOK*DINPROJ,
            0, 0, 0, 1);
        convbc_k<<<dim3(SEQ/64, 4), 32>>>(convw, convb, l);
        scanA_k<<<1024, 64>>>(Dp, dt_bias, A_log, convw, convb, l);
        scanC_k<<<1024, 64>>>(l);
        rms_hl_k<<<2*NTOK, 256>>>(normw, l);
        // out-proj split-K: z = dir*2 + khalf; K=512 per CTA, lda=DINNER
        gemm5<false, false><<<dim3(4, 16, 4), 256, GSMEM>>>(
            pyh, pyl,
            pwouth + (long)l*2*DINNER*DMODEL,
            nullptr, pyt, DMODEL, 512, DINNER,
            (long)NTOK*DINNER, (long)DINNER*DMODEL, 2L*NTOK*DMODEL,
            512, 512L*DMODEL, (long)NTOK*DMODEL, 2);
    }

    // final: LN(h + yt0..3) -> fp16 hi/lo + fp32 straight into out tail
    layernorm_hl_k<true><<<NTOK, 256>>>(ph, pyt,
        fn_w, fn_b, phfh, phfl, out + (long)NTOK*FEAT);
    gemm5<false, true><<<dim3(1, 16, 1), 256, GSMEM>>>(
        phfh, phfl, pwpoh, bpo, out, FEAT, DMODEL, DMODEL,
        0, 0, 0, 0, 0, 0, 1);
}